// round 2
// baseline (speedup 1.0000x reference)
#include <cuda_runtime.h>
#include <math.h>

// Problem constants (fixed shapes)
#define BATCH   16384
#define DIN     1024
#define DH      4096
#define NCLS    10
#define TAU_F   0.5f
#define T1_IT   3
#define T2_IT   3

#define BM 128
#define BN 128
#define BK 16
#define NTILES (DH / BN)          // 32 n-tiles per row

// Scratch: partial logits  [net][row][ntile][class]  = 2*16384*32*10*4 = 52 MB
__device__ float g_P[2][(size_t)BATCH * NTILES * NCLS];

// ---------------------------------------------------------------------------
// Fused stage 1: per CTA compute 128x128 tile of relu(X@W1+b1), then multiply
// by the matching 128x10 slice of W2 and emit partial logits. Hidden never
// touches HBM.
// ---------------------------------------------------------------------------
__global__ __launch_bounds__(256, 2)
void gemm_head_kernel(const float* __restrict__ X,
                      const float* __restrict__ W1,
                      const float* __restrict__ b1,
                      const float* __restrict__ W2,
                      int net)
{
    float* __restrict__ P = g_P[net];

    __shared__ float As[BK][BM + 4];     // pad: conflict-free column reads
    __shared__ float Bs[BK][BN];
    __shared__ float W2s[BN][NCLS];      // 5 KB slice of W2 for this n-tile

    const int tid = threadIdx.x;
    const int m0  = blockIdx.y * BM;
    const int n0  = blockIdx.x * BN;
    const int tx  = tid & 15;            // 16 thread-cols  (8 n each)
    const int ty  = tid >> 4;            // 16 thread-rows  (8 m each)

    // Preload this tile's W2 slice (visible after first __syncthreads)
    for (int s = tid; s < BN * NCLS; s += 256)
        W2s[s / NCLS][s % NCLS] = W2[(size_t)(n0 + s / NCLS) * NCLS + (s % NCLS)];

    float acc[8][8];
#pragma unroll
    for (int i = 0; i < 8; i++)
#pragma unroll
        for (int j = 0; j < 8; j++) acc[i][j] = 0.f;

    for (int k0 = 0; k0 < DIN; k0 += BK) {
#pragma unroll
        for (int s = 0; s < 2; s++) {
            int slot = tid + s * 256;    // 0..511
            int row = slot >> 2, kq = slot & 3;       // X: 4 float4 per 16-k row
            float4 v = *(const float4*)(X + (size_t)(m0 + row) * DIN + k0 + kq * 4);
            As[kq * 4 + 0][row] = v.x;
            As[kq * 4 + 1][row] = v.y;
            As[kq * 4 + 2][row] = v.z;
            As[kq * 4 + 3][row] = v.w;
            int krow = slot >> 5, nq = slot & 31;     // W1: 32 float4 per k-row
            *(float4*)(&Bs[krow][nq * 4]) =
                *(const float4*)(W1 + (size_t)(k0 + krow) * DH + n0 + nq * 4);
        }
        __syncthreads();

#pragma unroll
        for (int kk = 0; kk < BK; kk++) {
            float a[8], b[8];
#pragma unroll
            for (int i = 0; i < 8; i++) a[i] = As[kk][ty * 8 + i];
#pragma unroll
            for (int j = 0; j < 8; j++) b[j] = Bs[kk][tx * 8 + j];
#pragma unroll
            for (int i = 0; i < 8; i++)
#pragma unroll
                for (int j = 0; j < 8; j++)
                    acc[i][j] = fmaf(a[i], b[j], acc[i][j]);
        }
        __syncthreads();
    }

    // bias + ReLU in registers
    {
        float bv[8];
#pragma unroll
        for (int j = 0; j < 8; j++) bv[j] = b1[n0 + tx * 8 + j];
#pragma unroll
        for (int i = 0; i < 8; i++)
#pragma unroll
            for (int j = 0; j < 8; j++) {
                float v = acc[i][j] + bv[j];
                acc[i][j] = v > 0.f ? v : 0.f;
            }
    }

    // Partial logits: pl[row i][class c] = sum_j acc[i][j] * W2s[tx*8+j][c]
    // Process 2 classes at a time to bound register pressure (acc stays live).
#pragma unroll
    for (int c0 = 0; c0 < NCLS; c0 += 2) {
        float pl0[8], pl1[8];
#pragma unroll
        for (int i = 0; i < 8; i++) { pl0[i] = 0.f; pl1[i] = 0.f; }
#pragma unroll
        for (int j = 0; j < 8; j++) {
            float2 w = *(const float2*)&W2s[tx * 8 + j][c0];
#pragma unroll
            for (int i = 0; i < 8; i++) {
                pl0[i] = fmaf(acc[i][j], w.x, pl0[i]);
                pl1[i] = fmaf(acc[i][j], w.y, pl1[i]);
            }
        }
        // reduce across the 16 tx-threads of each row (lanes 0-15 / 16-31)
#pragma unroll
        for (int off = 8; off; off >>= 1) {
#pragma unroll
            for (int i = 0; i < 8; i++) {
                pl0[i] += __shfl_xor_sync(0xffffffffu, pl0[i], off);
                pl1[i] += __shfl_xor_sync(0xffffffffu, pl1[i], off);
            }
        }
        if (tx == 0) {
#pragma unroll
            for (int i = 0; i < 8; i++) {
                size_t base = ((size_t)(m0 + ty * 8 + i) * NTILES + blockIdx.x) * NCLS;
                P[base + c0]     = pl0[i];
                P[base + c0 + 1] = pl1[i];
            }
        }
    }
}

// ---------------------------------------------------------------------------
// Stage 2: reduce 32 partials per row (both nets), +b2, softmax,
// comp_max_tau, blend. Warp per row; lane = n-tile index.
// ---------------------------------------------------------------------------
__device__ __forceinline__ float inv_apprx_dev(float x, float m)
{
    float a = 2.f - (2.f / m) * x;
    float b = 1.f - (2.f / m) * x;
#pragma unroll
    for (int i = 0; i < T2_IT; i++) { b = b * b; a = a * (1.f + b); }
    return (2.f / m) * a;
}

__device__ __forceinline__ void softmax10(const float* z, float* p)
{
    float mx = z[0];
#pragma unroll
    for (int c = 1; c < NCLS; c++) mx = fmaxf(mx, z[c]);
    float s = 0.f;
#pragma unroll
    for (int c = 0; c < NCLS; c++) { p[c] = expf(z[c] - mx); s += p[c]; }
    float inv = 1.f / s;
#pragma unroll
    for (int c = 0; c < NCLS; c++) p[c] *= inv;
}

__global__ __launch_bounds__(256)
void reduce_head_kernel(const float* __restrict__ b2o,
                        const float* __restrict__ b2f,
                        float* __restrict__ out)
{
    const int row  = (blockIdx.x * blockDim.x + threadIdx.x) >> 5;
    const int lane = threadIdx.x & 31;
    if (row >= BATCH) return;

    const float* po = g_P[0] + ((size_t)row * NTILES + lane) * NCLS;
    const float* pf = g_P[1] + ((size_t)row * NTILES + lane) * NCLS;

    float zo[NCLS], zf[NCLS];
#pragma unroll
    for (int p = 0; p < 5; p++) {
        float2 vo = *(const float2*)(po + 2 * p);
        float2 vf = *(const float2*)(pf + 2 * p);
        zo[2 * p] = vo.x; zo[2 * p + 1] = vo.y;
        zf[2 * p] = vf.x; zf[2 * p + 1] = vf.y;
    }

#pragma unroll
    for (int c = 0; c < NCLS; c++) {
#pragma unroll
        for (int off = 16; off; off >>= 1) {
            zo[c] += __shfl_xor_sync(0xffffffffu, zo[c], off);
            zf[c] += __shfl_xor_sync(0xffffffffu, zf[c], off);
        }
    }

    if (lane == 0) {
        float lo[NCLS], lf[NCLS], pso[NCLS], psf[NCLS];
#pragma unroll
        for (int c = 0; c < NCLS; c++) { lo[c] = zo[c] + b2o[c]; lf[c] = zf[c] + b2f[c]; }
        softmax10(lo, pso);
        softmax10(lf, psf);

        float res[NCLS + 1];
#pragma unroll
        for (int c = 0; c < NCLS; c++) res[c] = pso[c];
        res[NCLS] = TAU_F;
#pragma unroll
        for (int i = 0; i < T1_IT; i++) {
            float s = 0.f;
#pragma unroll
            for (int j = 0; j < NCLS + 1; j++) { res[j] = res[j] * res[j]; s += res[j]; }
            float m = (i == 0) ? (2.f + TAU_F * TAU_F) : 2.f;
            float inv = inv_apprx_dev(s, m);
#pragma unroll
            for (int j = 0; j < NCLS + 1; j++) res[j] *= inv;
        }
        float cond = res[NCLS];

        float* o = out + (size_t)row * NCLS;
#pragma unroll
        for (int c = 0; c < NCLS; c++)
            o[c] = pso[c] * (1.f - cond) + psf[c] * cond;
    }
}

// ---------------------------------------------------------------------------
// kernel_launch
// ---------------------------------------------------------------------------
extern "C" void kernel_launch(void* const* d_in, const int* in_sizes, int n_in,
                              void* d_out, int out_size)
{
    const float* x   = (const float*)d_in[0];
    const float* W1o = (const float*)d_in[1];
    const float* b1o = (const float*)d_in[2];
    const float* W2o = (const float*)d_in[3];
    const float* b2o = (const float*)d_in[4];
    const float* W1f = (const float*)d_in[5];
    const float* b1f = (const float*)d_in[6];
    const float* W2f = (const float*)d_in[7];
    const float* b2f = (const float*)d_in[8];
    float* out = (float*)d_out;

    dim3 ggrid(NTILES, BATCH / BM);      // (32, 128)
    gemm_head_kernel<<<ggrid, 256>>>(x, W1o, b1o, W2o, 0);
    gemm_head_kernel<<<ggrid, 256>>>(x, W1f, b1f, W2f, 1);

    int nblocks = (BATCH * 32 + 255) / 256;   // warp per row
    reduce_head_kernel<<<nblocks, 256>>>(b2o, b2f, out);
}

// round 4
// speedup vs baseline: 2.8610x; 2.8610x over previous
#include <cuda_runtime.h>
#include <cuda_bf16.h>
#include <math.h>
#include <stdint.h>

// Problem constants
#define BATCH   16384
#define DIN     1024
#define DH      4096
#define NCLS    10
#define TAU_F   0.5f
#define T1_IT   3
#define T2_IT   3

#define BM 128
#define BN 128
#define NTILES (DH / BN)            // 32

// GEMM pipeline: K chunks of 64 bf16 (=128B rows), 3 segments (hh, hl, lh)
#define BKC     64
#define CH_SEG  (DIN / BKC)         // 16
#define NCHUNK  (3 * CH_SEG)        // 48
#define STG     3

// Dynamic SMEM layout (offsets from 1024-aligned base)
#define STAGE_BYTES 32768           // A 16KB + B 16KB (bf16 128x64)
#define OFF_STAGE(s) ((s) * STAGE_BYTES)
#define OFF_BTILE    16384
#define OFF_W2       98304          // 128*10 f32 = 5120
#define OFF_B1       103424         // 128 f32 = 512
#define DSMEM_BYTES  (1024 + 103936)

#define SWZ(o) ((o) ^ (((o) >> 3) & 0x70))

// Static scratch (no allocations)
__device__ __nv_bfloat16 g_Xh[(size_t)BATCH * DIN];          // 32 MB
__device__ __nv_bfloat16 g_Xl[(size_t)BATCH * DIN];          // 32 MB
__device__ __nv_bfloat16 g_WTh[2][(size_t)DH * DIN];         // 2 x 8 MB (K-major [N][K])
__device__ __nv_bfloat16 g_WTl[2][(size_t)DH * DIN];         // 2 x 8 MB
__device__ float g_P[2][(size_t)BATCH * NTILES * NCLS];      // 52 MB partial logits

// ---------------------------------------------------------------------------
// helpers
// ---------------------------------------------------------------------------
__device__ __forceinline__ uint32_t smem_u32(const void* p) {
    uint32_t a;
    asm("{ .reg .u64 t; cvta.to.shared.u64 t, %1; cvt.u32.u64 %0, t; }"
        : "=r"(a) : "l"(p));
    return a;
}

__device__ __forceinline__ void cp_async16(uint32_t dst, const void* src) {
    asm volatile("cp.async.cg.shared.global [%0], [%1], 16;" :: "r"(dst), "l"(src));
}
#define CP_COMMIT() asm volatile("cp.async.commit_group;" ::: "memory")
#define CP_WAIT2()  asm volatile("cp.async.wait_group 2;" ::: "memory")

__device__ __forceinline__ void ldsm_x4(uint32_t& r0, uint32_t& r1,
                                        uint32_t& r2, uint32_t& r3, uint32_t a) {
    asm volatile("ldmatrix.sync.aligned.m8n8.x4.shared.b16 {%0,%1,%2,%3}, [%4];"
                 : "=r"(r0), "=r"(r1), "=r"(r2), "=r"(r3) : "r"(a));
}

__device__ __forceinline__ void mma_bf16(float& c0, float& c1, float& c2, float& c3,
                                         uint32_t a0, uint32_t a1, uint32_t a2, uint32_t a3,
                                         uint32_t b0, uint32_t b1) {
    asm volatile("mma.sync.aligned.m16n8k16.row.col.f32.bf16.bf16.f32 "
                 "{%0,%1,%2,%3}, {%4,%5,%6,%7}, {%8,%9}, {%0,%1,%2,%3};"
                 : "+f"(c0), "+f"(c1), "+f"(c2), "+f"(c3)
                 : "r"(a0), "r"(a1), "r"(a2), "r"(a3), "r"(b0), "r"(b1));
}

// ---------------------------------------------------------------------------
// Pre-pass 1: split X -> bf16 hi/lo
// ---------------------------------------------------------------------------
__global__ void decompose_x_kernel(const float* __restrict__ X)
{
    int i = blockIdx.x * blockDim.x + threadIdx.x;   // float4 index, exact cover
    float4 v = ((const float4*)X)[i];
    __nv_bfloat162 h01, h23, l01, l23;
    float h;
    h = __bfloat162float(__float2bfloat16_rn(v.x)); h01.x = __float2bfloat16_rn(h); l01.x = __float2bfloat16_rn(v.x - h);
    h = __bfloat162float(__float2bfloat16_rn(v.y)); h01.y = __float2bfloat16_rn(h); l01.y = __float2bfloat16_rn(v.y - h);
    h = __bfloat162float(__float2bfloat16_rn(v.z)); h23.x = __float2bfloat16_rn(h); l23.x = __float2bfloat16_rn(v.z - h);
    h = __bfloat162float(__float2bfloat16_rn(v.w)); h23.y = __float2bfloat16_rn(h); l23.y = __float2bfloat16_rn(v.w - h);
    ((__nv_bfloat162*)g_Xh)[2 * i]     = h01;
    ((__nv_bfloat162*)g_Xh)[2 * i + 1] = h23;
    ((__nv_bfloat162*)g_Xl)[2 * i]     = l01;
    ((__nv_bfloat162*)g_Xl)[2 * i + 1] = l23;
}

// ---------------------------------------------------------------------------
// Pre-pass 2: transpose W1 [K,N] -> [N,K], split bf16 hi/lo
// ---------------------------------------------------------------------------
__global__ void wsplit_kernel(const float* __restrict__ W, int net)
{
    __shared__ __nv_bfloat16 th[32][33], tl[32][33];
    int tx = threadIdx.x, ty = threadIdx.y;          // (32, 8)
    int n  = blockIdx.x * 32 + tx;
    int k0 = blockIdx.y * 32;
#pragma unroll
    for (int i = 0; i < 32; i += 8) {
        float v = W[(size_t)(k0 + ty + i) * DH + n];
        __nv_bfloat16 hb = __float2bfloat16_rn(v);
        th[ty + i][tx] = hb;
        tl[ty + i][tx] = __float2bfloat16_rn(v - __bfloat162float(hb));
    }
    __syncthreads();
    int kk = k0 + tx;
    int nn = blockIdx.x * 32 + ty;
    __nv_bfloat16* Th = g_WTh[net];
    __nv_bfloat16* Tl = g_WTl[net];
#pragma unroll
    for (int i = 0; i < 32; i += 8) {
        Th[(size_t)(nn + i) * DIN + kk] = th[tx][ty + i];
        Tl[(size_t)(nn + i) * DIN + kk] = tl[tx][ty + i];
    }
}

// ---------------------------------------------------------------------------
// Main GEMM: 128x128 tile, bf16 split-3 via mma.sync, cp.async 3-stage pipe,
// fused epilogue (bias+ReLU+W2 partial logits -> g_P).
// ---------------------------------------------------------------------------
__global__ __launch_bounds__(256, 2)
void gemm_bf16_kernel(const float* __restrict__ b1,
                      const float* __restrict__ W2,
                      int net)
{
    extern __shared__ char dsm_raw[];
    const uint32_t raw  = smem_u32(dsm_raw);
    const uint32_t base = (raw + 1023) & ~1023u;
    char* gbase = dsm_raw + (base - raw);

    const int tid  = threadIdx.x;
    const int wid  = tid >> 5;
    const int lane = tid & 31;
    const int wm   = wid & 1;            // 2 warps over M (64 rows each)
    const int wn   = wid >> 1;           // 4 warps over N (32 cols each)
    const int m0   = blockIdx.y * BM;
    const int n0   = blockIdx.x * BN;

    const __nv_bfloat16* __restrict__ Ah = g_Xh;
    const __nv_bfloat16* __restrict__ Al = g_Xl;
    const __nv_bfloat16* __restrict__ Wh = g_WTh[net];
    const __nv_bfloat16* __restrict__ Wl = g_WTl[net];

    // epilogue constants
    float* W2s = (float*)(gbase + OFF_W2);
    float* b1s = (float*)(gbase + OFF_B1);
    for (int i = tid; i < BN * NCLS; i += 256)
        W2s[i] = W2[(size_t)(n0 + i / NCLS) * NCLS + (i % NCLS)];
    if (tid < BN) b1s[tid] = b1[n0 + tid];

    float acc[4][4][4];
#pragma unroll
    for (int i = 0; i < 4; i++)
#pragma unroll
        for (int j = 0; j < 4; j++)
#pragma unroll
            for (int r = 0; r < 4; r++) acc[i][j][r] = 0.f;

    auto produce = [&](int cc) {
        const int seg = cc / CH_SEG;
        const int kc  = (cc % CH_SEG) * BKC;
        const __nv_bfloat16* As = (seg < 2) ? Ah : Al;
        const __nv_bfloat16* Bs = (seg == 1) ? Wl : Wh;
        const uint32_t st = base + OFF_STAGE(cc % STG);
#pragma unroll
        for (int i = 0; i < 4; i++) {
            int q = i * 256 + tid;                    // 0..1023
            int row = q >> 3, g = q & 7;              // 8 x 16B per 128B row
            cp_async16(st + SWZ(row * 128 + g * 16),
                       As + (size_t)(m0 + row) * DIN + kc + g * 8);
        }
#pragma unroll
        for (int i = 0; i < 4; i++) {
            int q = i * 256 + tid;
            int row = q >> 3, g = q & 7;
            cp_async16(st + OFF_BTILE + SWZ(row * 128 + g * 16),
                       Bs + (size_t)(n0 + row) * DIN + kc + g * 8);
        }
    };

    produce(0); CP_COMMIT();
    produce(1); CP_COMMIT();

    const int lrow = lane & 7;
    const int lsel = lane >> 3;                        // 0..3

    for (int c = 0; c < NCHUNK; c++) {
        if (c + 2 < NCHUNK) produce(c + 2);
        CP_COMMIT();
        CP_WAIT2();
        __syncthreads();

        const uint32_t stA = base + OFF_STAGE(c % STG);
        const uint32_t stB = stA + OFF_BTILE;

#pragma unroll
        for (int ks = 0; ks < 4; ks++) {               // 4 x k16 per 64-K chunk
            const int k0 = ks * 16;

            // A fragments: 4 m-tiles of 16 rows
            uint32_t a[4][4];
#pragma unroll
            for (int mt = 0; mt < 4; mt++) {
                int row = wm * 64 + mt * 16 + lrow + (lsel & 1) * 8;
                int kof = (lsel >> 1) * 8;
                ldsm_x4(a[mt][0], a[mt][1], a[mt][2], a[mt][3],
                        stA + SWZ(row * 128 + (k0 + kof) * 2));
            }
            // B fragments: 2 x4 loads cover 4 n-tiles of 8
            uint32_t b[4][2];
#pragma unroll
            for (int np = 0; np < 2; np++) {
                int row = wn * 32 + np * 16 + lrow + (lsel >> 1) * 8;
                int kof = (lsel & 1) * 8;
                ldsm_x4(b[np * 2][0], b[np * 2][1], b[np * 2 + 1][0], b[np * 2 + 1][1],
                        stB + SWZ(row * 128 + (k0 + kof) * 2));
            }
#pragma unroll
            for (int mt = 0; mt < 4; mt++)
#pragma unroll
                for (int nt = 0; nt < 4; nt++)
                    mma_bf16(acc[mt][nt][0], acc[mt][nt][1], acc[mt][nt][2], acc[mt][nt][3],
                             a[mt][0], a[mt][1], a[mt][2], a[mt][3],
                             b[nt][0], b[nt][1]);
        }
        __syncthreads();   // protect stage reuse (write-after-read)
    }

    // ---- epilogue: fragments -> smem H tile (bias+ReLU), then partial logits
    __syncthreads();
    float* Hs = (float*)(gbase + 0);                   // [128][130], aliases stages
#pragma unroll
    for (int mt = 0; mt < 4; mt++) {
#pragma unroll
        for (int nt = 0; nt < 4; nt++) {
            int r0 = wm * 64 + mt * 16 + (lane >> 2);
            int cb = wn * 32 + nt * 8 + (lane & 3) * 2;
            float2 v0, v1;
            v0.x = fmaxf(acc[mt][nt][0] + b1s[cb],     0.f);
            v0.y = fmaxf(acc[mt][nt][1] + b1s[cb + 1], 0.f);
            v1.x = fmaxf(acc[mt][nt][2] + b1s[cb],     0.f);
            v1.y = fmaxf(acc[mt][nt][3] + b1s[cb + 1], 0.f);
            *(float2*)&Hs[r0 * 130 + cb]       = v0;
            *(float2*)&Hs[(r0 + 8) * 130 + cb] = v1;
        }
    }
    __syncthreads();

    if (tid < BM) {
        float pl[NCLS];
#pragma unroll
        for (int cc = 0; cc < NCLS; cc++) pl[cc] = 0.f;
        const float* hrow = &Hs[tid * 130];
        for (int n = 0; n < BN; n++) {
            float h = hrow[n];
            const float* w = &W2s[n * NCLS];
#pragma unroll
            for (int cc = 0; cc < NCLS; cc++)
                pl[cc] = fmaf(h, w[cc], pl[cc]);
        }
        float* P = g_P[net];
        size_t pb = ((size_t)(m0 + tid) * NTILES + blockIdx.x) * NCLS;
#pragma unroll
        for (int p = 0; p < 5; p++)
            *(float2*)(P + pb + 2 * p) = make_float2(pl[2 * p], pl[2 * p + 1]);
    }
}

// ---------------------------------------------------------------------------
// Stage 2: reduce partials, +b2, softmax, comp_max_tau, blend
// ---------------------------------------------------------------------------
__device__ __forceinline__ float inv_apprx_dev(float x, float m)
{
    float a = 2.f - (2.f / m) * x;
    float b = 1.f - (2.f / m) * x;
#pragma unroll
    for (int i = 0; i < T2_IT; i++) { b = b * b; a = a * (1.f + b); }
    return (2.f / m) * a;
}

__device__ __forceinline__ void softmax10(const float* z, float* p)
{
    float mx = z[0];
#pragma unroll
    for (int c = 1; c < NCLS; c++) mx = fmaxf(mx, z[c]);
    float s = 0.f;
#pragma unroll
    for (int c = 0; c < NCLS; c++) { p[c] = expf(z[c] - mx); s += p[c]; }
    float inv = 1.f / s;
#pragma unroll
    for (int c = 0; c < NCLS; c++) p[c] *= inv;
}

__global__ __launch_bounds__(256)
void reduce_head_kernel(const float* __restrict__ b2o,
                        const float* __restrict__ b2f,
                        float* __restrict__ out)
{
    const int row  = (blockIdx.x * blockDim.x + threadIdx.x) >> 5;
    const int lane = threadIdx.x & 31;
    if (row >= BATCH) return;

    const float* po = g_P[0] + ((size_t)row * NTILES + lane) * NCLS;
    const float* pf = g_P[1] + ((size_t)row * NTILES + lane) * NCLS;

    float zo[NCLS], zf[NCLS];
#pragma unroll
    for (int p = 0; p < 5; p++) {
        float2 vo = *(const float2*)(po + 2 * p);
        float2 vf = *(const float2*)(pf + 2 * p);
        zo[2 * p] = vo.x; zo[2 * p + 1] = vo.y;
        zf[2 * p] = vf.x; zf[2 * p + 1] = vf.y;
    }

#pragma unroll
    for (int c = 0; c < NCLS; c++) {
#pragma unroll
        for (int off = 16; off; off >>= 1) {
            zo[c] += __shfl_xor_sync(0xffffffffu, zo[c], off);
            zf[c] += __shfl_xor_sync(0xffffffffu, zf[c], off);
        }
    }

    if (lane == 0) {
        float lo[NCLS], lf[NCLS], pso[NCLS], psf[NCLS];
#pragma unroll
        for (int c = 0; c < NCLS; c++) { lo[c] = zo[c] + b2o[c]; lf[c] = zf[c] + b2f[c]; }
        softmax10(lo, pso);
        softmax10(lf, psf);

        float res[NCLS + 1];
#pragma unroll
        for (int c = 0; c < NCLS; c++) res[c] = pso[c];
        res[NCLS] = TAU_F;
#pragma unroll
        for (int i = 0; i < T1_IT; i++) {
            float s = 0.f;
#pragma unroll
            for (int j = 0; j < NCLS + 1; j++) { res[j] = res[j] * res[j]; s += res[j]; }
            float m = (i == 0) ? (2.f + TAU_F * TAU_F) : 2.f;
            float inv = inv_apprx_dev(s, m);
#pragma unroll
            for (int j = 0; j < NCLS + 1; j++) res[j] *= inv;
        }
        float cond = res[NCLS];

        float* o = out + (size_t)row * NCLS;
#pragma unroll
        for (int c = 0; c < NCLS; c++)
            o[c] = pso[c] * (1.f - cond) + psf[c] * cond;
    }
}

// ---------------------------------------------------------------------------
// kernel_launch
// ---------------------------------------------------------------------------
extern "C" void kernel_launch(void* const* d_in, const int* in_sizes, int n_in,
                              void* d_out, int out_size)
{
    const float* x   = (const float*)d_in[0];
    const float* W1o = (const float*)d_in[1];
    const float* b1o = (const float*)d_in[2];
    const float* W2o = (const float*)d_in[3];
    const float* b2o = (const float*)d_in[4];
    const float* W1f = (const float*)d_in[5];
    const float* b1f = (const float*)d_in[6];
    const float* W2f = (const float*)d_in[7];
    const float* b2f = (const float*)d_in[8];
    float* out = (float*)d_out;

    cudaFuncSetAttribute(gemm_bf16_kernel,
                         cudaFuncAttributeMaxDynamicSharedMemorySize, DSMEM_BYTES);

    decompose_x_kernel<<<(BATCH * DIN / 4) / 256, 256>>>(x);
    wsplit_kernel<<<dim3(DH / 32, DIN / 32), dim3(32, 8)>>>(W1o, 0);
    wsplit_kernel<<<dim3(DH / 32, DIN / 32), dim3(32, 8)>>>(W1f, 1);

    dim3 ggrid(NTILES, BATCH / BM);      // (32, 128)
    gemm_bf16_kernel<<<ggrid, 256, DSMEM_BYTES>>>(b1o, W2o, 0);
    gemm_bf16_kernel<<<ggrid, 256, DSMEM_BYTES>>>(b1f, W2f, 1);

    reduce_head_kernel<<<(BATCH * 32) / 256, 256>>>(b2o, b2f, out);
}